// round 13
// baseline (speedup 1.0000x reference)
#include <cuda_runtime.h>
#include <cuda_fp16.h>
#include <cstdint>

#define IN_DIM  256
#define OUT_DIM 64
#define HEADS   4
#define ZDIM    256          // HEADS * OUT_DIM
#define MAXN    50000
#define MAXE    800000

// ---------------- device scratch ------------------------------------------------
// g_deg is zero at module load; scan_add re-zeroes it each call after use, so the
// "g_deg == 0 at kernel_launch entry" invariant holds deterministically every call.
__device__ __half   g_zh[MAXN * ZDIM];     // projected features, fp16 [N, 256]
__device__ float    g_es[MAXN * HEADS];    // per-node src logits
__device__ float    g_ed[MAXN * HEADS];    // per-node dst logits
__device__ uint32_t g_wh[(IN_DIM / 2) * ZDIM];  // W pre-packed: [k2][n] = (W[2k2][o], W[2k2+1][o])
__device__ int      g_deg[MAXN];
__device__ int      g_off[MAXN];           // CSR offsets; post-scatter holds off[i+1]
__device__ int      g_part[256];           // block totals for scan
__device__ int      g_srcs[MAXE];          // CSR-scattered source ids

// ---------------- fp16 helpers ---------------------------------------------------
__device__ __forceinline__ uint32_t pack2_h(float a, float b) {
    __half2 v = __floats2half2_rn(a, b);
    return *reinterpret_cast<uint32_t*>(&v);
}

__device__ __forceinline__ void mma_f16(float* c, const uint32_t* a, uint32_t b0, uint32_t b1) {
    asm volatile(
        "mma.sync.aligned.m16n8k16.row.col.f32.f16.f16.f32 "
        "{%0,%1,%2,%3}, {%4,%5,%6,%7}, {%8,%9}, {%0,%1,%2,%3};"
        : "+f"(c[0]), "+f"(c[1]), "+f"(c[2]), "+f"(c[3])
        : "r"(a[0]), "r"(a[1]), "r"(a[2]), "r"(a[3]), "r"(b0), "r"(b1));
}

// ---------------- K0: pack W once: g_wh[k2*256+n] = (W[2k2][o], W[2k2+1][o]) -----
__global__ __launch_bounds__(256) void pack_W(const float* __restrict__ W) {
    int i = blockIdx.x * blockDim.x + threadIdx.x;   // 0 .. 32767
    int k2 = i >> 8;          // 0..127
    int n  = i & 255;
    int head = n >> 6, o = n & 63;
    const float* wp = W + head * (IN_DIM * OUT_DIM) + (2 * k2) * OUT_DIM + o;
    g_wh[i] = pack2_h(wp[0], wp[OUT_DIM]);
}

// ---------------- K1: z = h @ Wcat, plain fp16 GEMM, BN=256 single pass ----------
// BM=128, BN=256, BK=16. 512 threads = 16 warps: 4xM x 4xN (warp tile 32x64).
// A loaded + converted ONCE per row block; B copied raw from pre-packed g_wh.
#define SMPADA 136
#define SMPADB 264
#define NKT    (IN_DIM / 16)
__global__ __launch_bounds__(512) void gemm_z_tc(const float* __restrict__ h,
                                                 const float* __restrict__ a_src,
                                                 const float* __restrict__ a_dst, int M) {
    __shared__ uint32_t Ah[2][8][SMPADA];
    __shared__ uint32_t Bh[2][8][SMPADB];
    const int rowBase = blockIdx.x * 128;
    const int t    = threadIdx.x;
    const int lane = t & 31;
    const int warp = t >> 5;                 // 0..15
    const int wm = (warp & 3) * 32;          // M offset within 128
    const int wn = (warp >> 2) * 64;         // N offset within 256 (= head*64)

    const int aRow = t >> 2;                 // 0..127
    const int aK0  = (t & 3) * 4;            // 0,4,8,12
    const int bK2  = t >> 6;                 // 0..7
    const int bN   = (t & 63) * 4;           // 0..252

    float c[2][8][4];
#pragma unroll
    for (int i = 0; i < 2; i++)
#pragma unroll
        for (int j = 0; j < 8; j++)
#pragma unroll
            for (int k = 0; k < 4; k++) c[i][j][k] = 0.f;

    float4 av;
    uint4  bq;

    auto load_tile = [&](int kBase) {
        av = make_float4(0.f, 0.f, 0.f, 0.f);
        int gr = rowBase + aRow;
        if (gr < M) av = *(const float4*)(h + (size_t)gr * IN_DIM + kBase + aK0);
        bq = *(const uint4*)(g_wh + (kBase / 2 + bK2) * ZDIM + bN);
    };
    auto store_tile = [&](int buf) {
        Ah[buf][aK0 / 2][aRow]     = pack2_h(av.x, av.y);
        Ah[buf][aK0 / 2 + 1][aRow] = pack2_h(av.z, av.w);
        *(uint4*)&Bh[buf][bK2][bN] = bq;
    };

    load_tile(0);
    store_tile(0);

    for (int kt = 0; kt < NKT; kt++) {
        __syncthreads();
        if (kt + 1 < NKT) load_tile((kt + 1) * 16);

        const int buf = kt & 1;
        const int kp = lane & 3;
        uint32_t ah[2][4];
#pragma unroll
        for (int mt = 0; mt < 2; mt++) {
            int r = wm + mt * 16 + (lane >> 2);
            ah[mt][0] = Ah[buf][kp][r];
            ah[mt][1] = Ah[buf][kp][r + 8];
            ah[mt][2] = Ah[buf][kp + 4][r];
            ah[mt][3] = Ah[buf][kp + 4][r + 8];
        }
#pragma unroll
        for (int nt = 0; nt < 8; nt++) {
            int cn = wn + nt * 8 + (lane >> 2);
            uint32_t b0 = Bh[buf][kp][cn], b1 = Bh[buf][kp + 4][cn];
#pragma unroll
            for (int mt = 0; mt < 2; mt++) {
                mma_f16(c[mt][nt], ah[mt], b0, b1);
            }
        }
        if (kt + 1 < NKT) store_tile((kt + 1) & 1);
    }

    // ---------------- epilogue: write z (fp16) + fused es/ed ------------------
    const int head = wn >> 6;
    float cs[8][2], cd[8][2];
    {
        const float* ap = a_src + head * OUT_DIM;
        const float* dp = a_dst + head * OUT_DIM;
#pragma unroll
        for (int nt = 0; nt < 8; nt++) {
            int c0 = nt * 8 + (lane & 3) * 2;
            cs[nt][0] = ap[c0]; cs[nt][1] = ap[c0 + 1];
            cd[nt][0] = dp[c0]; cd[nt][1] = dp[c0 + 1];
        }
    }

#pragma unroll
    for (int mt = 0; mt < 2; mt++) {
        int r0 = rowBase + wm + mt * 16 + (lane >> 2);
        int r1 = r0 + 8;
        float es0 = 0.f, es1 = 0.f, ed0 = 0.f, ed1 = 0.f;
#pragma unroll
        for (int nt = 0; nt < 8; nt++) {
            int col = wn + nt * 8 + (lane & 3) * 2;
            if (r0 < M) {
                __half2 hz = __floats2half2_rn(c[mt][nt][0], c[mt][nt][1]);
                *(__half2*)(g_zh + (size_t)r0 * ZDIM + col) = hz;
            }
            if (r1 < M) {
                __half2 hz = __floats2half2_rn(c[mt][nt][2], c[mt][nt][3]);
                *(__half2*)(g_zh + (size_t)r1 * ZDIM + col) = hz;
            }
            es0 += c[mt][nt][0] * cs[nt][0] + c[mt][nt][1] * cs[nt][1];
            ed0 += c[mt][nt][0] * cd[nt][0] + c[mt][nt][1] * cd[nt][1];
            es1 += c[mt][nt][2] * cs[nt][0] + c[mt][nt][3] * cs[nt][1];
            ed1 += c[mt][nt][2] * cd[nt][0] + c[mt][nt][3] * cd[nt][1];
        }
#pragma unroll
        for (int off = 1; off < 4; off <<= 1) {
            es0 += __shfl_xor_sync(0xffffffffu, es0, off);
            ed0 += __shfl_xor_sync(0xffffffffu, ed0, off);
            es1 += __shfl_xor_sync(0xffffffffu, es1, off);
            ed1 += __shfl_xor_sync(0xffffffffu, ed1, off);
        }
        if ((lane & 3) == 0) {
            if (r0 < M) { g_es[r0 * HEADS + head] = es0; g_ed[r0 * HEADS + head] = ed0; }
            if (r1 < M) { g_es[r1 * HEADS + head] = es1; g_ed[r1 * HEADS + head] = ed1; }
        }
    }
}

// ---------------- K2: degree histogram (vectorized; g_deg pre-zeroed) ------------
__global__ void edge_deg(const int* __restrict__ dst, int E) {
    int i = (blockIdx.x * blockDim.x + threadIdx.x) * 4;
    if (i + 3 < E) {
        int4 d = *(const int4*)(dst + i);
        atomicAdd(&g_deg[d.x], 1);
        atomicAdd(&g_deg[d.y], 1);
        atomicAdd(&g_deg[d.z], 1);
        atomicAdd(&g_deg[d.w], 1);
    } else {
        for (; i < E; i++) atomicAdd(&g_deg[dst[i]], 1);
    }
}

// ---------------- K3a: per-block scan (512 nodes/block), totals -> g_part --------
__global__ __launch_bounds__(512) void scan_part(int N) {
    __shared__ int ws[16];
    int t   = threadIdx.x;
    int idx = blockIdx.x * 512 + t;
    int orig = (idx < N) ? g_deg[idx] : 0;
    int v = orig;
    int lane = t & 31, wid = t >> 5;
#pragma unroll
    for (int off = 1; off < 32; off <<= 1) {
        int n = __shfl_up_sync(0xffffffffu, v, off);
        if (lane >= off) v += n;
    }
    if (lane == 31) ws[wid] = v;
    __syncthreads();
    if (wid == 0) {
        int x = (lane < 16) ? ws[lane] : 0;
#pragma unroll
        for (int off = 1; off < 16; off <<= 1) {
            int n = __shfl_up_sync(0xffffffffu, x, off);
            if (lane >= off) x += n;
        }
        if (lane < 16) ws[lane] = x;
    }
    __syncthreads();
    int excl = v - orig + (wid ? ws[wid - 1] : 0);
    if (idx < N) g_off[idx] = excl;
    if (t == 511) g_part[blockIdx.x] = excl + orig;   // block total
}

// ---------------- K3b: add block prefix (self-summed) + re-zero deg --------------
__global__ __launch_bounds__(512) void scan_add(int N) {
    __shared__ int prefix_s;
    int t = threadIdx.x;
    if (t < 32) {
        int sum = 0;
        for (int j = t; j < blockIdx.x; j += 32) sum += g_part[j];
#pragma unroll
        for (int off = 16; off; off >>= 1) sum += __shfl_xor_sync(0xffffffffu, sum, off);
        if (t == 0) prefix_s = sum;
    }
    __syncthreads();
    int idx = blockIdx.x * 512 + t;
    if (idx < N) {
        g_off[idx] += prefix_s;
        g_deg[idx] = 0;     // restore the zero-at-entry invariant for the next call
    }
}

// ---------------- K4: CSR src scatter --------------------------------------------
__global__ void edge_scatter(const int* __restrict__ src, const int* __restrict__ dst, int E) {
    int i = (blockIdx.x * blockDim.x + threadIdx.x) * 4;
    if (i + 3 < E) {
        int4 s = *(const int4*)(src + i);
        int4 d = *(const int4*)(dst + i);
        g_srcs[atomicAdd(&g_off[d.x], 1)] = s.x;
        g_srcs[atomicAdd(&g_off[d.y], 1)] = s.y;
        g_srcs[atomicAdd(&g_off[d.z], 1)] = s.z;
        g_srcs[atomicAdd(&g_off[d.w], 1)] = s.w;
    } else {
        for (; i < E; i++) g_srcs[atomicAdd(&g_off[dst[i]], 1)] = src[i];
    }
}

// ---------------- K5: aggregation, fp16 z, 4x unroll + src prefetch --------------
__global__ void aggregate(float* __restrict__ out, int N) {
    int node = (blockIdx.x * blockDim.x + threadIdx.x) >> 5;
    int lane = threadIdx.x & 31;
    if (node >= N) return;
    int beg = node ? g_off[node - 1] : 0;
    int end = g_off[node];
    int head = lane >> 3;
    float edv = g_ed[node * HEADS + head];

    float acc[8] = {0.f, 0.f, 0.f, 0.f, 0.f, 0.f, 0.f, 0.f};
    float wsum = 0.f;
    const __half* zbase = g_zh;

    int i = beg;
    int s0 = 0, s1 = 0, s2 = 0, s3 = 0;
    bool have = (i + 3 < end);
    if (have) {
        s0 = g_srcs[i]; s1 = g_srcs[i + 1]; s2 = g_srcs[i + 2]; s3 = g_srcs[i + 3];
    }
    while (have) {
        int ni = i + 4;
        bool nhave = (ni + 3 < end);
        int t0 = 0, t1 = 0, t2 = 0, t3 = 0;
        if (nhave) {
            t0 = g_srcs[ni]; t1 = g_srcs[ni + 1]; t2 = g_srcs[ni + 2]; t3 = g_srcs[ni + 3];
        }
        float e0 = g_es[s0 * HEADS + head] + edv;
        float e1 = g_es[s1 * HEADS + head] + edv;
        float e2 = g_es[s2 * HEADS + head] + edv;
        float e3 = g_es[s3 * HEADS + head] + edv;
        uint4 v0 = *(const uint4*)(zbase + (size_t)s0 * ZDIM + lane * 8);
        uint4 v1 = *(const uint4*)(zbase + (size_t)s1 * ZDIM + lane * 8);
        uint4 v2 = *(const uint4*)(zbase + (size_t)s2 * ZDIM + lane * 8);
        uint4 v3 = *(const uint4*)(zbase + (size_t)s3 * ZDIM + lane * 8);
        e0 = e0 > 0.f ? e0 : 0.01f * e0;
        e1 = e1 > 0.f ? e1 : 0.01f * e1;
        e2 = e2 > 0.f ? e2 : 0.01f * e2;
        e3 = e3 > 0.f ? e3 : 0.01f * e3;
        float w0 = __expf(e0), w1 = __expf(e1), w2 = __expf(e2), w3 = __expf(e3);
        wsum += (w0 + w1) + (w2 + w3);
        float2 f;
        f = __half22float2(*(__half2*)&v0.x); acc[0] += w0 * f.x; acc[1] += w0 * f.y;
        f = __half22float2(*(__half2*)&v0.y); acc[2] += w0 * f.x; acc[3] += w0 * f.y;
        f = __half22float2(*(__half2*)&v0.z); acc[4] += w0 * f.x; acc[5] += w0 * f.y;
        f = __half22float2(*(__half2*)&v0.w); acc[6] += w0 * f.x; acc[7] += w0 * f.y;
        f = __half22float2(*(__half2*)&v1.x); acc[0] += w1 * f.x; acc[1] += w1 * f.y;
        f = __half22float2(*(__half2*)&v1.y); acc[2] += w1 * f.x; acc[3] += w1 * f.y;
        f = __half22float2(*(__half2*)&v1.z); acc[4] += w1 * f.x; acc[5] += w1 * f.y;
        f = __half22float2(*(__half2*)&v1.w); acc[6] += w1 * f.x; acc[7] += w1 * f.y;
        f = __half22float2(*(__half2*)&v2.x); acc[0] += w2 * f.x; acc[1] += w2 * f.y;
        f = __half22float2(*(__half2*)&v2.y); acc[2] += w2 * f.x; acc[3] += w2 * f.y;
        f = __half22float2(*(__half2*)&v2.z); acc[4] += w2 * f.x; acc[5] += w2 * f.y;
        f = __half22float2(*(__half2*)&v2.w); acc[6] += w2 * f.x; acc[7] += w2 * f.y;
        f = __half22float2(*(__half2*)&v3.x); acc[0] += w3 * f.x; acc[1] += w3 * f.y;
        f = __half22float2(*(__half2*)&v3.y); acc[2] += w3 * f.x; acc[3] += w3 * f.y;
        f = __half22float2(*(__half2*)&v3.z); acc[4] += w3 * f.x; acc[5] += w3 * f.y;
        f = __half22float2(*(__half2*)&v3.w); acc[6] += w3 * f.x; acc[7] += w3 * f.y;
        s0 = t0; s1 = t1; s2 = t2; s3 = t3;
        i = ni; have = nhave;
    }
    for (; i < end; i++) {
        int sx = g_srcs[i];
        float e0 = g_es[sx * HEADS + head] + edv;
        e0 = e0 > 0.f ? e0 : 0.01f * e0;
        float w0 = __expf(e0);
        uint4 v0 = *(const uint4*)(zbase + (size_t)sx * ZDIM + lane * 8);
        wsum += w0;
        float2 f;
        f = __half22float2(*(__half2*)&v0.x); acc[0] += w0 * f.x; acc[1] += w0 * f.y;
        f = __half22float2(*(__half2*)&v0.y); acc[2] += w0 * f.x; acc[3] += w0 * f.y;
        f = __half22float2(*(__half2*)&v0.z); acc[4] += w0 * f.x; acc[5] += w0 * f.y;
        f = __half22float2(*(__half2*)&v0.w); acc[6] += w0 * f.x; acc[7] += w0 * f.y;
    }

    float inv = (end > beg) ? (1.f / wsum) : 0.f;
    float* dst = out + (size_t)node * ZDIM + lane * 8;
    *(float4*)(dst)     = make_float4(acc[0] * inv, acc[1] * inv, acc[2] * inv, acc[3] * inv);
    *(float4*)(dst + 4) = make_float4(acc[4] * inv, acc[5] * inv, acc[6] * inv, acc[7] * inv);
}

// ---------------- launch ---------------------------------------------------------
extern "C" void kernel_launch(void* const* d_in, const int* in_sizes, int n_in,
                              void* d_out, int out_size) {
    const float* h     = (const float*)d_in[0];
    const int*   src   = (const int*)d_in[1];
    const int*   dst   = (const int*)d_in[2];
    const float* W     = (const float*)d_in[3];
    const float* a_src = (const float*)d_in[4];
    const float* a_dst = (const float*)d_in[5];
    float* out = (float*)d_out;

    const int N = in_sizes[0] / IN_DIM;
    const int E = in_sizes[1];

    static cudaStream_t s2 = nullptr;
    static cudaEvent_t evFork = nullptr, evJoin = nullptr;
    static bool init_done = false;
    if (!init_done) {
        if (cudaStreamCreateWithFlags(&s2, cudaStreamNonBlocking) != cudaSuccess) s2 = nullptr;
        if (s2) {
            if (cudaEventCreateWithFlags(&evFork, cudaEventDisableTiming) != cudaSuccess ||
                cudaEventCreateWithFlags(&evJoin, cudaEventDisableTiming) != cudaSuccess) {
                s2 = nullptr;
            }
        }
        init_done = true;
    }

    const bool fork = (s2 != nullptr);
    cudaStream_t sB = fork ? s2 : (cudaStream_t)0;

    if (fork) {
        cudaEventRecord(evFork, 0);
        cudaStreamWaitEvent(s2, evFork, 0);
    }

    // stream B (independent of GEMM): histogram + scan (g_deg arrives zeroed)
    int degBlocks = ((E + 3) / 4 + 255) / 256;
    edge_deg<<<degBlocks, 256, 0, sB>>>(dst, E);
    int nb = (N + 511) / 512;
    scan_part<<<nb, 512, 0, sB>>>(N);
    scan_add<<<nb, 512, 0, sB>>>(N);

    // stream 0: W pre-pack, then single-pass BN=256 GEMM + fused logits
    pack_W<<<(IN_DIM / 2) * ZDIM / 256, 256>>>(W);
    int gBlocks = (N + 127) / 128;
    gemm_z_tc<<<gBlocks, 512>>>(h, a_src, a_dst, N);

    // stream B: scatter
    edge_scatter<<<degBlocks, 256, 0, sB>>>(src, dst, E);

    if (fork) {
        cudaEventRecord(evJoin, s2);
        cudaStreamWaitEvent(0, evJoin, 0);
    }

    // stream 0: aggregate (needs GEMM results + CSR)
    int nodeBlocks = (N * 32 + 255) / 256;
    aggregate<<<nodeBlocks, 256>>>(out, N);
}

// round 14
// speedup vs baseline: 1.0413x; 1.0413x over previous
#include <cuda_runtime.h>
#include <cuda_fp16.h>
#include <cstdint>

#define IN_DIM  256
#define OUT_DIM 64
#define HEADS   4
#define ZDIM    256          // HEADS * OUT_DIM
#define MAXN    50000
#define MAXE    800000

// ---------------- device scratch ------------------------------------------------
// g_deg is zero at module load; scan_add re-zeroes it each call after use, so the
// "g_deg == 0 at kernel_launch entry" invariant holds deterministically every call.
__device__ __half   g_zh[MAXN * ZDIM];     // projected features, fp16 [N, 256]
__device__ float    g_es[MAXN * HEADS];    // per-node src logits
__device__ float    g_ed[MAXN * HEADS];    // per-node dst logits
__device__ uint32_t g_wh[(IN_DIM / 2) * ZDIM];  // W pre-packed: [k2][n] = (W[2k2][o], W[2k2+1][o])
__device__ int      g_deg[MAXN];
__device__ int      g_off[MAXN];           // CSR offsets; post-scatter holds off[i+1]
__device__ int      g_part[256];           // block totals for scan
__device__ int      g_srcs[MAXE];          // CSR-scattered source ids

// ---------------- fp16 helpers ---------------------------------------------------
__device__ __forceinline__ uint32_t pack2_h(float a, float b) {
    __half2 v = __floats2half2_rn(a, b);
    return *reinterpret_cast<uint32_t*>(&v);
}

__device__ __forceinline__ void mma_f16(float* c, const uint32_t* a, uint32_t b0, uint32_t b1) {
    asm volatile(
        "mma.sync.aligned.m16n8k16.row.col.f32.f16.f16.f32 "
        "{%0,%1,%2,%3}, {%4,%5,%6,%7}, {%8,%9}, {%0,%1,%2,%3};"
        : "+f"(c[0]), "+f"(c[1]), "+f"(c[2]), "+f"(c[3])
        : "r"(a[0]), "r"(a[1]), "r"(a[2]), "r"(a[3]), "r"(b0), "r"(b1));
}

__device__ __forceinline__ void cp_async16(uint32_t smem_addr, const void* gptr) {
    asm volatile("cp.async.cg.shared.global [%0], [%1], 16;"
                 :: "r"(smem_addr), "l"(gptr));
}
#define CP_COMMIT() asm volatile("cp.async.commit_group;" ::: "memory")
#define CP_WAIT0()  asm volatile("cp.async.wait_group 0;" ::: "memory")

// ---------------- K0: pack W once: g_wh[k2*256+n] = (W[2k2][o], W[2k2+1][o]) -----
__global__ __launch_bounds__(256) void pack_W(const float* __restrict__ W) {
    int i = blockIdx.x * blockDim.x + threadIdx.x;   // 0 .. 32767
    int k2 = i >> 8;          // 0..127
    int n  = i & 255;
    int head = n >> 6, o = n & 63;
    const float* wp = W + head * (IN_DIM * OUT_DIM) + (2 * k2) * OUT_DIM + o;
    g_wh[i] = pack2_h(wp[0], wp[OUT_DIM]);
}

// ---------------- K1: z = h @ Wcat, fp16 GEMM, BK=32, cp.async B -----------------
// BM=128, BN=128, BK=32. 8 warps: 4xM, 2xN(=head). 2-stage smem pipeline:
// A register-prefetch (fp32->fp16 cvt), B streamed via cp.async from g_wh.
// 8 k-iterations (half the barriers of BK=16), 2 k16 MMA groups per iteration.
#define SMPAD 136
#define NKT   (IN_DIM / 32)
__global__ __launch_bounds__(256) void gemm_z_tc(const float* __restrict__ h,
                                                 const float* __restrict__ a_src,
                                                 const float* __restrict__ a_dst, int M) {
    __shared__ uint32_t Ah[2][16][SMPAD];
    __shared__ uint32_t Bh[2][16][SMPAD];
    const int rowBase = blockIdx.x * 128;
    const int nBase0  = blockIdx.y * 128;
    const int t    = threadIdx.x;
    const int lane = t & 31;
    const int warp = t >> 5;
    const int wm = (warp & 3) * 32;
    const int wn = (warp >> 2) * 64;

    // A: thread t loads row t>>1, k half (t&1)*16 .. +15 (4 float4)
    const int aRow = t >> 1;
    const int aKb  = (t & 1) * 16;
    // B: thread t streams k2 rows bK2 and bK2+8, 4 cols at bN
    const int bK2  = t >> 5;                  // 0..7
    const int bN   = (t & 31) * 4;
    const int bCol = nBase0 + bN;

    float c[2][8][4];
#pragma unroll
    for (int i = 0; i < 2; i++)
#pragma unroll
        for (int j = 0; j < 8; j++)
#pragma unroll
            for (int k = 0; k < 4; k++) c[i][j][k] = 0.f;

    float4 av[4];

    auto load_a = [&](int kBase) {
        int gr = rowBase + aRow;
        if (gr < M) {
            const float* hp = h + (size_t)gr * IN_DIM + kBase + aKb;
#pragma unroll
            for (int i = 0; i < 4; i++) av[i] = *(const float4*)(hp + i * 4);
        } else {
#pragma unroll
            for (int i = 0; i < 4; i++) av[i] = make_float4(0.f, 0.f, 0.f, 0.f);
        }
    };
    auto store_a = [&](int buf) {
#pragma unroll
        for (int i = 0; i < 4; i++) {
            int k2 = (aKb >> 1) + i * 2;
            Ah[buf][k2][aRow]     = pack2_h(av[i].x, av[i].y);
            Ah[buf][k2 + 1][aRow] = pack2_h(av[i].z, av[i].w);
        }
    };
    auto load_b_async = [&](int kBase, int buf) {
        const uint32_t* src0 = g_wh + (kBase / 2 + bK2) * ZDIM + bCol;
        const uint32_t* src1 = g_wh + (kBase / 2 + bK2 + 8) * ZDIM + bCol;
        cp_async16((uint32_t)__cvta_generic_to_shared(&Bh[buf][bK2][bN]), src0);
        cp_async16((uint32_t)__cvta_generic_to_shared(&Bh[buf][bK2 + 8][bN]), src1);
        CP_COMMIT();
    };

    // prologue: tile 0
    load_a(0);
    load_b_async(0, 0);
    store_a(0);
    CP_WAIT0();

    for (int kt = 0; kt < NKT; kt++) {
        __syncthreads();
        if (kt + 1 < NKT) {
            load_a((kt + 1) * 32);
            load_b_async((kt + 1) * 32, (kt + 1) & 1);
        }

        const int buf = kt & 1;
        const int kp = lane & 3;
#pragma unroll
        for (int g = 0; g < 2; g++) {
            const int kb = g * 8;
            uint32_t ah[2][4];
#pragma unroll
            for (int mt = 0; mt < 2; mt++) {
                int r = wm + mt * 16 + (lane >> 2);
                ah[mt][0] = Ah[buf][kb + kp][r];
                ah[mt][1] = Ah[buf][kb + kp][r + 8];
                ah[mt][2] = Ah[buf][kb + kp + 4][r];
                ah[mt][3] = Ah[buf][kb + kp + 4][r + 8];
            }
#pragma unroll
            for (int nt = 0; nt < 8; nt++) {
                int cn = wn + nt * 8 + (lane >> 2);
                uint32_t b0 = Bh[buf][kb + kp][cn], b1 = Bh[buf][kb + kp + 4][cn];
#pragma unroll
                for (int mt = 0; mt < 2; mt++) {
                    mma_f16(c[mt][nt], ah[mt], b0, b1);
                }
            }
        }
        if (kt + 1 < NKT) {
            store_a((kt + 1) & 1);
            CP_WAIT0();
        }
    }

    // ---------------- epilogue: write z (fp16) + fused es/ed ------------------
    const int head = (nBase0 + wn) >> 6;
    float cs[8][2], cd[8][2];
    {
        const float* ap = a_src + head * OUT_DIM;
        const float* dp = a_dst + head * OUT_DIM;
#pragma unroll
        for (int nt = 0; nt < 8; nt++) {
            int c0 = nt * 8 + (lane & 3) * 2;
            cs[nt][0] = ap[c0]; cs[nt][1] = ap[c0 + 1];
            cd[nt][0] = dp[c0]; cd[nt][1] = dp[c0 + 1];
        }
    }

#pragma unroll
    for (int mt = 0; mt < 2; mt++) {
        int r0 = rowBase + wm + mt * 16 + (lane >> 2);
        int r1 = r0 + 8;
        float es0 = 0.f, es1 = 0.f, ed0 = 0.f, ed1 = 0.f;
#pragma unroll
        for (int nt = 0; nt < 8; nt++) {
            int col = nBase0 + wn + nt * 8 + (lane & 3) * 2;
            if (r0 < M) {
                __half2 hz = __floats2half2_rn(c[mt][nt][0], c[mt][nt][1]);
                *(__half2*)(g_zh + (size_t)r0 * ZDIM + col) = hz;
            }
            if (r1 < M) {
                __half2 hz = __floats2half2_rn(c[mt][nt][2], c[mt][nt][3]);
                *(__half2*)(g_zh + (size_t)r1 * ZDIM + col) = hz;
            }
            es0 += c[mt][nt][0] * cs[nt][0] + c[mt][nt][1] * cs[nt][1];
            ed0 += c[mt][nt][0] * cd[nt][0] + c[mt][nt][1] * cd[nt][1];
            es1 += c[mt][nt][2] * cs[nt][0] + c[mt][nt][3] * cs[nt][1];
            ed1 += c[mt][nt][2] * cd[nt][0] + c[mt][nt][3] * cd[nt][1];
        }
#pragma unroll
        for (int off = 1; off < 4; off <<= 1) {
            es0 += __shfl_xor_sync(0xffffffffu, es0, off);
            ed0 += __shfl_xor_sync(0xffffffffu, ed0, off);
            es1 += __shfl_xor_sync(0xffffffffu, es1, off);
            ed1 += __shfl_xor_sync(0xffffffffu, ed1, off);
        }
        if ((lane & 3) == 0) {
            if (r0 < M) { g_es[r0 * HEADS + head] = es0; g_ed[r0 * HEADS + head] = ed0; }
            if (r1 < M) { g_es[r1 * HEADS + head] = es1; g_ed[r1 * HEADS + head] = ed1; }
        }
    }
}

// ---------------- K2: degree histogram (vectorized; g_deg pre-zeroed) ------------
__global__ void edge_deg(const int* __restrict__ dst, int E) {
    int i = (blockIdx.x * blockDim.x + threadIdx.x) * 4;
    if (i + 3 < E) {
        int4 d = *(const int4*)(dst + i);
        atomicAdd(&g_deg[d.x], 1);
        atomicAdd(&g_deg[d.y], 1);
        atomicAdd(&g_deg[d.z], 1);
        atomicAdd(&g_deg[d.w], 1);
    } else {
        for (; i < E; i++) atomicAdd(&g_deg[dst[i]], 1);
    }
}

// ---------------- K3a: per-block scan (512 nodes/block), totals -> g_part --------
__global__ __launch_bounds__(512) void scan_part(int N) {
    __shared__ int ws[16];
    int t   = threadIdx.x;
    int idx = blockIdx.x * 512 + t;
    int orig = (idx < N) ? g_deg[idx] : 0;
    int v = orig;
    int lane = t & 31, wid = t >> 5;
#pragma unroll
    for (int off = 1; off < 32; off <<= 1) {
        int n = __shfl_up_sync(0xffffffffu, v, off);
        if (lane >= off) v += n;
    }
    if (lane == 31) ws[wid] = v;
    __syncthreads();
    if (wid == 0) {
        int x = (lane < 16) ? ws[lane] : 0;
#pragma unroll
        for (int off = 1; off < 16; off <<= 1) {
            int n = __shfl_up_sync(0xffffffffu, x, off);
            if (lane >= off) x += n;
        }
        if (lane < 16) ws[lane] = x;
    }
    __syncthreads();
    int excl = v - orig + (wid ? ws[wid - 1] : 0);
    if (idx < N) g_off[idx] = excl;
    if (t == 511) g_part[blockIdx.x] = excl + orig;   // block total
}

// ---------------- K3b: add block prefix (self-summed) + re-zero deg --------------
__global__ __launch_bounds__(512) void scan_add(int N) {
    __shared__ int prefix_s;
    int t = threadIdx.x;
    if (t < 32) {
        int sum = 0;
        for (int j = t; j < blockIdx.x; j += 32) sum += g_part[j];
#pragma unroll
        for (int off = 16; off; off >>= 1) sum += __shfl_xor_sync(0xffffffffu, sum, off);
        if (t == 0) prefix_s = sum;
    }
    __syncthreads();
    int idx = blockIdx.x * 512 + t;
    if (idx < N) {
        g_off[idx] += prefix_s;
        g_deg[idx] = 0;     // restore the zero-at-entry invariant for the next call
    }
}

// ---------------- K4: CSR src scatter --------------------------------------------
__global__ void edge_scatter(const int* __restrict__ src, const int* __restrict__ dst, int E) {
    int i = (blockIdx.x * blockDim.x + threadIdx.x) * 4;
    if (i + 3 < E) {
        int4 s = *(const int4*)(src + i);
        int4 d = *(const int4*)(dst + i);
        g_srcs[atomicAdd(&g_off[d.x], 1)] = s.x;
        g_srcs[atomicAdd(&g_off[d.y], 1)] = s.y;
        g_srcs[atomicAdd(&g_off[d.z], 1)] = s.z;
        g_srcs[atomicAdd(&g_off[d.w], 1)] = s.w;
    } else {
        for (; i < E; i++) g_srcs[atomicAdd(&g_off[dst[i]], 1)] = src[i];
    }
}

// ---------------- K5: aggregation, fp16 z, 4x unroll + src prefetch --------------
__global__ void aggregate(float* __restrict__ out, int N) {
    int node = (blockIdx.x * blockDim.x + threadIdx.x) >> 5;
    int lane = threadIdx.x & 31;
    if (node >= N) return;
    int beg = node ? g_off[node - 1] : 0;
    int end = g_off[node];
    int head = lane >> 3;
    float edv = g_ed[node * HEADS + head];

    float acc[8] = {0.f, 0.f, 0.f, 0.f, 0.f, 0.f, 0.f, 0.f};
    float wsum = 0.f;
    const __half* zbase = g_zh;

    int i = beg;
    int s0 = 0, s1 = 0, s2 = 0, s3 = 0;
    bool have = (i + 3 < end);
    if (have) {
        s0 = g_srcs[i]; s1 = g_srcs[i + 1]; s2 = g_srcs[i + 2]; s3 = g_srcs[i + 3];
    }
    while (have) {
        int ni = i + 4;
        bool nhave = (ni + 3 < end);
        int t0 = 0, t1 = 0, t2 = 0, t3 = 0;
        if (nhave) {
            t0 = g_srcs[ni]; t1 = g_srcs[ni + 1]; t2 = g_srcs[ni + 2]; t3 = g_srcs[ni + 3];
        }
        float e0 = g_es[s0 * HEADS + head] + edv;
        float e1 = g_es[s1 * HEADS + head] + edv;
        float e2 = g_es[s2 * HEADS + head] + edv;
        float e3 = g_es[s3 * HEADS + head] + edv;
        uint4 v0 = *(const uint4*)(zbase + (size_t)s0 * ZDIM + lane * 8);
        uint4 v1 = *(const uint4*)(zbase + (size_t)s1 * ZDIM + lane * 8);
        uint4 v2 = *(const uint4*)(zbase + (size_t)s2 * ZDIM + lane * 8);
        uint4 v3 = *(const uint4*)(zbase + (size_t)s3 * ZDIM + lane * 8);
        e0 = e0 > 0.f ? e0 : 0.01f * e0;
        e1 = e1 > 0.f ? e1 : 0.01f * e1;
        e2 = e2 > 0.f ? e2 : 0.01f * e2;
        e3 = e3 > 0.f ? e3 : 0.01f * e3;
        float w0 = __expf(e0), w1 = __expf(e1), w2 = __expf(e2), w3 = __expf(e3);
        wsum += (w0 + w1) + (w2 + w3);
        float2 f;
        f = __half22float2(*(__half2*)&v0.x); acc[0] += w0 * f.x; acc[1] += w0 * f.y;
        f = __half22float2(*(__half2*)&v0.y); acc[2] += w0 * f.x; acc[3] += w0 * f.y;
        f = __half22float2(*(__half2*)&v0.z); acc[4] += w0 * f.x; acc[5] += w0 * f.y;
        f = __half22float2(*(__half2*)&v0.w); acc[6] += w0 * f.x; acc[7] += w0 * f.y;
        f = __half22float2(*(__half2*)&v1.x); acc[0] += w1 * f.x; acc[1] += w1 * f.y;
        f = __half22float2(*(__half2*)&v1.y); acc[2] += w1 * f.x; acc[3] += w1 * f.y;
        f = __half22float2(*(__half2*)&v1.z); acc[4] += w1 * f.x; acc[5] += w1 * f.y;
        f = __half22float2(*(__half2*)&v1.w); acc[6] += w1 * f.x; acc[7] += w1 * f.y;
        f = __half22float2(*(__half2*)&v2.x); acc[0] += w2 * f.x; acc[1] += w2 * f.y;
        f = __half22float2(*(__half2*)&v2.y); acc[2] += w2 * f.x; acc[3] += w2 * f.y;
        f = __half22float2(*(__half2*)&v2.z); acc[4] += w2 * f.x; acc[5] += w2 * f.y;
        f = __half22float2(*(__half2*)&v2.w); acc[6] += w2 * f.x; acc[7] += w2 * f.y;
        f = __half22float2(*(__half2*)&v3.x); acc[0] += w3 * f.x; acc[1] += w3 * f.y;
        f = __half22float2(*(__half2*)&v3.y); acc[2] += w3 * f.x; acc[3] += w3 * f.y;
        f = __half22float2(*(__half2*)&v3.z); acc[4] += w3 * f.x; acc[5] += w3 * f.y;
        f = __half22float2(*(__half2*)&v3.w); acc[6] += w3 * f.x; acc[7] += w3 * f.y;
        s0 = t0; s1 = t1; s2 = t2; s3 = t3;
        i = ni; have = nhave;
    }
    for (; i < end; i++) {
        int sx = g_srcs[i];
        float e0 = g_es[sx * HEADS + head] + edv;
        e0 = e0 > 0.f ? e0 : 0.01f * e0;
        float w0 = __expf(e0);
        uint4 v0 = *(const uint4*)(zbase + (size_t)sx * ZDIM + lane * 8);
        wsum += w0;
        float2 f;
        f = __half22float2(*(__half2*)&v0.x); acc[0] += w0 * f.x; acc[1] += w0 * f.y;
        f = __half22float2(*(__half2*)&v0.y); acc[2] += w0 * f.x; acc[3] += w0 * f.y;
        f = __half22float2(*(__half2*)&v0.z); acc[4] += w0 * f.x; acc[5] += w0 * f.y;
        f = __half22float2(*(__half2*)&v0.w); acc[6] += w0 * f.x; acc[7] += w0 * f.y;
    }

    float inv = (end > beg) ? (1.f / wsum) : 0.f;
    float* dst = out + (size_t)node * ZDIM + lane * 8;
    *(float4*)(dst)     = make_float4(acc[0] * inv, acc[1] * inv, acc[2] * inv, acc[3] * inv);
    *(float4*)(dst + 4) = make_float4(acc[4] * inv, acc[5] * inv, acc[6] * inv, acc[7] * inv);
}

// ---------------- launch ---------------------------------------------------------
extern "C" void kernel_launch(void* const* d_in, const int* in_sizes, int n_in,
                              void* d_out, int out_size) {
    const float* h     = (const float*)d_in[0];
    const int*   src   = (const int*)d_in[1];
    const int*   dst   = (const int*)d_in[2];
    const float* W     = (const float*)d_in[3];
    const float* a_src = (const float*)d_in[4];
    const float* a_dst = (const float*)d_in[5];
    float* out = (float*)d_out;

    const int N = in_sizes[0] / IN_DIM;
    const int E = in_sizes[1];

    static cudaStream_t s2 = nullptr;
    static cudaEvent_t evFork = nullptr, evJoin = nullptr;
    static bool init_done = false;
    if (!init_done) {
        if (cudaStreamCreateWithFlags(&s2, cudaStreamNonBlocking) != cudaSuccess) s2 = nullptr;
        if (s2) {
            if (cudaEventCreateWithFlags(&evFork, cudaEventDisableTiming) != cudaSuccess ||
                cudaEventCreateWithFlags(&evJoin, cudaEventDisableTiming) != cudaSuccess) {
                s2 = nullptr;
            }
        }
        init_done = true;
    }

    const bool fork = (s2 != nullptr);
    cudaStream_t sB = fork ? s2 : (cudaStream_t)0;

    if (fork) {
        cudaEventRecord(evFork, 0);
        cudaStreamWaitEvent(s2, evFork, 0);
    }

    // stream B (independent of GEMM): histogram + scan (g_deg arrives zeroed)
    int degBlocks = ((E + 3) / 4 + 255) / 256;
    edge_deg<<<degBlocks, 256, 0, sB>>>(dst, E);
    int nb = (N + 511) / 512;
    scan_part<<<nb, 512, 0, sB>>>(N);
    scan_add<<<nb, 512, 0, sB>>>(N);

    // stream 0: W pre-pack, then BK=32 GEMM + fused logits
    pack_W<<<(IN_DIM / 2) * ZDIM / 256, 256>>>(W);
    dim3 ggrid((N + 127) / 128, ZDIM / 128);
    gemm_z_tc<<<ggrid, 256>>>(h, a_src, a_dst, N);

    // stream B: scatter
    edge_scatter<<<degBlocks, 256, 0, sB>>>(src, dst, E);

    if (fork) {
        cudaEventRecord(evJoin, s2);
        cudaStreamWaitEvent(0, evJoin, 0);
    }

    // stream 0: aggregate (needs GEMM results + CSR)
    int nodeBlocks = (N * 32 + 255) / 256;
    aggregate<<<nodeBlocks, 256>>>(out, N);
}